// round 1
// baseline (speedup 1.0000x reference)
#include <cuda_runtime.h>
#include <math.h>

#define NROW 8192
#define NC   128          // feature dim
#define BI   64           // i-rows per CTA
#define BJ   128          // j-cols per tile
#define NTHREADS 512
#define TILE_STRIDE 132   // floats per smem row (16B aligned, bank-step 4)
#define SMEM_BYTES (((BI + BJ) * TILE_STRIDE) * 4 + BJ * 4)

__device__ float g_xn[NROW * NC];   // normalized x
__device__ float g_row[NROW];       // per-row loss

// ---------------------------------------------------------------------------
// Kernel 1: L2-normalize rows. One warp per row (128 floats = 32 lanes x float4).
// ---------------------------------------------------------------------------
__global__ void __launch_bounds__(256) normalize_kernel(const float* __restrict__ x) {
    int row  = blockIdx.x * 8 + (threadIdx.x >> 5);
    int lane = threadIdx.x & 31;
    float4 v = reinterpret_cast<const float4*>(x)[row * 32 + lane];
    float ss = v.x * v.x + v.y * v.y + v.z * v.z + v.w * v.w;
#pragma unroll
    for (int o = 16; o; o >>= 1) ss += __shfl_xor_sync(0xffffffffu, ss, o);
    float inv = 1.0f / fmaxf(sqrtf(ss), 1e-12f);
    v.x *= inv; v.y *= inv; v.z *= inv; v.w *= inv;
    reinterpret_cast<float4*>(g_xn)[row * 32 + lane] = v;
}

// ---------------------------------------------------------------------------
// Kernel 2: fused Gram + per-row contrastive stats.
// Grid: 128 CTAs (one 64-row i-block each), 512 threads (16 warps).
// Each CTA sweeps all j in tiles of 128. Thread (tx,ty) owns micro-tile
// rows i = ty + 16r, cols j = tx + 32c (r,c in 0..3).
// A/B smem tiles row-major with 132-float stride: conflict-free LDS.128.
// ---------------------------------------------------------------------------
__global__ void __launch_bounds__(NTHREADS) scl_main_kernel(const int* __restrict__ y) {
    extern __shared__ float smem[];
    float* As = smem;                               // BI x TILE_STRIDE
    float* Bs = smem + BI * TILE_STRIDE;            // BJ x TILE_STRIDE
    int*  yjs = (int*)(smem + (BI + BJ) * TILE_STRIDE);

    const float4* xg4 = reinterpret_cast<const float4*>(g_xn);
    float4* As4 = reinterpret_cast<float4*>(As);
    float4* Bs4 = reinterpret_cast<float4*>(Bs);

    const int tid   = threadIdx.x;
    const int tx    = tid & 31;
    const int ty    = tid >> 5;
    const int ibase = blockIdx.x * BI;

    // Load A tile once: BI*32 float4, coalesced (lanes sweep k4).
#pragma unroll
    for (int t = 0; t < (BI * 32) / NTHREADS; ++t) {
        int idx = tid + t * NTHREADS;
        int i = idx >> 5, k4 = idx & 31;
        As4[i * (TILE_STRIDE / 4) + k4] = xg4[(ibase + i) * 32 + k4];
    }

    int   yiv[4];
    float denomP[4] = {0.f, 0.f, 0.f, 0.f};
    float SP[4]     = {0.f, 0.f, 0.f, 0.f};
    float mP[4]     = {0.f, 0.f, 0.f, 0.f};
#pragma unroll
    for (int r = 0; r < 4; ++r) yiv[r] = y[ibase + ty + 16 * r];

    for (int jt = 0; jt < NROW / BJ; ++jt) {
        const int jbase = jt * BJ;
        __syncthreads();   // previous tile fully consumed
        // Load B tile: BJ*32 float4, coalesced.
#pragma unroll
        for (int t = 0; t < (BJ * 32) / NTHREADS; ++t) {
            int idx = tid + t * NTHREADS;
            int j = idx >> 5, k4 = idx & 31;
            Bs4[j * (TILE_STRIDE / 4) + k4] = xg4[(jbase + j) * 32 + k4];
        }
        if (tid < BJ) yjs[tid] = y[jbase + tid];
        __syncthreads();

        float acc[4][4];
#pragma unroll
        for (int r = 0; r < 4; ++r)
#pragma unroll
            for (int c = 0; c < 4; ++c) acc[r][c] = 0.f;

#pragma unroll 4
        for (int k4 = 0; k4 < 32; ++k4) {
            float4 a[4], b[4];
#pragma unroll
            for (int r = 0; r < 4; ++r)
                a[r] = As4[(ty + 16 * r) * (TILE_STRIDE / 4) + k4];   // warp broadcast
#pragma unroll
            for (int c = 0; c < 4; ++c)
                b[c] = Bs4[(tx + 32 * c) * (TILE_STRIDE / 4) + k4];   // conflict-free
#pragma unroll
            for (int r = 0; r < 4; ++r)
#pragma unroll
                for (int c = 0; c < 4; ++c) {
                    acc[r][c] += a[r].x * b[c].x;
                    acc[r][c] += a[r].y * b[c].y;
                    acc[r][c] += a[r].z * b[c].z;
                    acc[r][c] += a[r].w * b[c].w;
                }
        }

        // Fold this tile's dots into per-row running stats.
        int yjv[4];
#pragma unroll
        for (int c = 0; c < 4; ++c) yjv[c] = yjs[tx + 32 * c];
#pragma unroll
        for (int r = 0; r < 4; ++r) {
            const int ig = ibase + ty + 16 * r;
#pragma unroll
            for (int c = 0; c < 4; ++c) {
                const int jg = jbase + tx + 32 * c;
                const float d = acc[r][c];
                const bool diag = (jg == ig);
                const float e = __expf(d * 10.0f);        // 1/T = 10
                if (!diag) denomP[r] += e;
                if (!diag && (yjv[c] == yiv[r])) {
                    SP[r] += d;
                    mP[r] += 1.0f;
                }
            }
        }
    }

    // Warp-level reduction across tx lanes; each warp exclusively owns its 4 rows.
#pragma unroll
    for (int r = 0; r < 4; ++r) {
        float d = denomP[r], s = SP[r], m = mP[r];
#pragma unroll
        for (int o = 16; o; o >>= 1) {
            d += __shfl_xor_sync(0xffffffffu, d, o);
            s += __shfl_xor_sync(0xffffffffu, s, o);
            m += __shfl_xor_sync(0xffffffffu, m, o);
        }
        if (tx == 0) {
            // row_i = -(S/T - m*log(denom))/max(m,1) ; m==0 -> 0
            float row = (m > 0.5f) ? (logf(d) - (s * 10.0f) / m) : 0.0f;
            g_row[ibase + ty + 16 * r] = row;
        }
    }
}

// ---------------------------------------------------------------------------
// Kernel 3: deterministic final reduction of g_row -> scalar.
// ---------------------------------------------------------------------------
__global__ void __launch_bounds__(256) reduce_kernel(float* __restrict__ out) {
    __shared__ float sm[256];
    float s = 0.f;
    for (int i = threadIdx.x; i < NROW; i += 256) s += g_row[i];
    sm[threadIdx.x] = s;
    __syncthreads();
#pragma unroll
    for (int o = 128; o; o >>= 1) {
        if (threadIdx.x < o) sm[threadIdx.x] += sm[threadIdx.x + o];
        __syncthreads();
    }
    if (threadIdx.x == 0) out[0] = sm[0];
}

// ---------------------------------------------------------------------------
extern "C" void kernel_launch(void* const* d_in, const int* in_sizes, int n_in,
                              void* d_out, int out_size) {
    (void)in_sizes; (void)n_in; (void)out_size;
    const float* x = (const float*)d_in[0];
    const int*   y = (const int*)d_in[1];
    float* out = (float*)d_out;

    cudaFuncSetAttribute(scl_main_kernel,
                         cudaFuncAttributeMaxDynamicSharedMemorySize, SMEM_BYTES);

    normalize_kernel<<<NROW / 8, 256>>>(x);
    scl_main_kernel<<<NROW / BI, NTHREADS, SMEM_BYTES>>>(y);
    reduce_kernel<<<1, 256>>>(out);
}

// round 6
// speedup vs baseline: 5.3336x; 5.3336x over previous
#include <cuda_runtime.h>
#include <cuda_bf16.h>
#include <stdint.h>
#include <math.h>

#define NROW 8192
#define THREADS 512
#define STRIDE_B 272u            // bytes per smem tile row (136 bf16, 17x16B -> conflict-free)
#define TILE_BYTES (128u * STRIDE_B)      // 34816
#define A_OFF  0u
#define B_OFF  TILE_BYTES
#define YJ_OFF (TILE_BYTES * 3u)          // 2 slots x 512B
#define SD_OFF (YJ_OFF + 1024u)           // 3 x 512 floats
#define SMEM_TOTAL (SD_OFF + 3u * 2048u)

__device__ __nv_bfloat16 g_xb[NROW * 128];
__device__ float g_pd[2 * NROW];
__device__ float g_ps[2 * NROW];
__device__ float g_pm[2 * NROW];

// ---------------- PTX helpers ----------------
__device__ __forceinline__ uint32_t smem_u32(const void* p) {
    uint32_t a;
    asm("{ .reg .u64 t; cvta.to.shared.u64 t, %1; cvt.u32.u64 %0, t; }" : "=r"(a) : "l"(p));
    return a;
}
#define LDSM4(r, a) \
    asm volatile("ldmatrix.sync.aligned.m8n8.x4.shared.b16 {%0,%1,%2,%3}, [%4];" \
        : "=r"((r)[0]), "=r"((r)[1]), "=r"((r)[2]), "=r"((r)[3]) : "r"(a))
#define MMA16816(c, a, b0v, b1v) \
    asm volatile("mma.sync.aligned.m16n8k16.row.col.f32.bf16.bf16.f32 " \
        "{%0,%1,%2,%3}, {%4,%5,%6,%7}, {%8,%9}, {%0,%1,%2,%3};" \
        : "+f"((c)[0]), "+f"((c)[1]), "+f"((c)[2]), "+f"((c)[3]) \
        : "r"((a)[0]), "r"((a)[1]), "r"((a)[2]), "r"((a)[3]), "r"(b0v), "r"(b1v))
#define CP_ASYNC16(dst, src) \
    asm volatile("cp.async.cg.shared.global [%0], [%1], 16;" :: "r"(dst), "l"(src))
#define CP_ASYNC4(dst, src) \
    asm volatile("cp.async.ca.shared.global [%0], [%1], 4;" :: "r"(dst), "l"(src))
#define CP_COMMIT() asm volatile("cp.async.commit_group;" ::: "memory")
#define CP_WAIT1()  asm volatile("cp.async.wait_group 1;" ::: "memory")

// ---------------- Kernel 1: normalize + bf16 convert ----------------
__global__ void __launch_bounds__(256) norm_kernel(const float* __restrict__ x) {
    int row = blockIdx.x * 8 + (threadIdx.x >> 5);
    int lane = threadIdx.x & 31;
    float4 v = reinterpret_cast<const float4*>(x)[row * 32 + lane];
    float ss = v.x * v.x + v.y * v.y + v.z * v.z + v.w * v.w;
#pragma unroll
    for (int o = 16; o; o >>= 1) ss += __shfl_xor_sync(0xffffffffu, ss, o);
    float inv = 1.0f / fmaxf(sqrtf(ss), 1e-12f);
    v.x *= inv; v.y *= inv; v.z *= inv; v.w *= inv;
    uint32_t p0 = ((uint32_t)__bfloat16_as_ushort(__float2bfloat16(v.y)) << 16)
                |  (uint32_t)__bfloat16_as_ushort(__float2bfloat16(v.x));
    uint32_t p1 = ((uint32_t)__bfloat16_as_ushort(__float2bfloat16(v.w)) << 16)
                |  (uint32_t)__bfloat16_as_ushort(__float2bfloat16(v.z));
    reinterpret_cast<uint2*>(g_xb)[row * 32 + lane] = make_uint2(p0, p1);
}

// ---------------- Kernel 2: mma.sync Gram + fused stats ----------------
__global__ void __launch_bounds__(THREADS, 1) scl_mma_kernel(const int* __restrict__ y) {
    extern __shared__ char smem[];
    const uint32_t sbase = smem_u32(smem);
    const int tid = threadIdx.x, wid = tid >> 5, lane = tid & 31;
    const int wi = wid & 3, wj = wid >> 2;       // 4x4 warp grid: 32x32 out per warp
    const int ibase = blockIdx.x * 128;
    const int jorig = blockIdx.y * (NROW / 2);   // 32 j-tiles of 128

    const uint4* xg = reinterpret_cast<const uint4*>(g_xb);   // 16 x 16B chunks/row

    // --- A tile: plain loads, swizzle-free padded layout ---
#pragma unroll
    for (int q = 0; q < 4; ++q) {
        int idx = tid + q * THREADS;
        int row = idx >> 4, c16 = idx & 15;
        *reinterpret_cast<uint4*>(smem + A_OFF + row * STRIDE_B + c16 * 16) =
            xg[(ibase + row) * 16 + c16];
    }

    // --- prologue: async-prefetch B tiles 0 and 1 ---
#pragma unroll
    for (int b = 0; b < 2; ++b) {
        uint32_t dstb = sbase + B_OFF + (uint32_t)b * TILE_BYTES;
        const int jb = jorig + b * 128;
#pragma unroll
        for (int q = 0; q < 4; ++q) {
            int idx = tid + q * THREADS;
            int row = idx >> 4, c16 = idx & 15;
            CP_ASYNC16(dstb + row * STRIDE_B + c16 * 16,
                       (const void*)(xg + (jb + row) * 16 + c16));
        }
        if (tid < 128) CP_ASYNC4(sbase + YJ_OFF + (uint32_t)b * 512 + tid * 4,
                                 (const void*)(y + jb + tid));
        CP_COMMIT();
    }

    // per-thread ldmatrix base addresses
    const int grp = lane >> 2;                  // accum row group
    uint32_t aAddr[2], bAddr[2];
#pragma unroll
    for (int mi = 0; mi < 2; ++mi)
        aAddr[mi] = sbase + A_OFF + (uint32_t)((wi * 32 + mi * 16 + (lane & 15)) * STRIDE_B
                    + (lane >> 4) * 16);
#pragma unroll
    for (int nb = 0; nb < 2; ++nb)
        bAddr[nb] = sbase + B_OFF + (uint32_t)((wj * 32 + nb * 16 + (lane & 7) + (lane >> 4) * 8) * STRIDE_B
                    + ((lane >> 3) & 1) * 16);

    // i rows owned by this thread: ibase + wi*32 + mi*16 + rh*8 + grp
    int   yiv[2][2];
    float dnm[2][2] = {{0.f,0.f},{0.f,0.f}};
    float Ssum[2][2] = {{0.f,0.f},{0.f,0.f}};
    float msum[2][2] = {{0.f,0.f},{0.f,0.f}};
#pragma unroll
    for (int mi = 0; mi < 2; ++mi)
#pragma unroll
        for (int rh = 0; rh < 2; ++rh)
            yiv[mi][rh] = y[ibase + wi * 32 + mi * 16 + rh * 8 + grp];

    for (int t = 0; t < 32; ++t) {
        CP_WAIT1();
        __syncthreads();                        // B(t) + yj(t) visible everywhere
        const uint32_t bufoff = (uint32_t)(t & 1) * TILE_BYTES;
        const int jbase = jorig + t * 128;

        float acc[2][4][4];
#pragma unroll
        for (int mi = 0; mi < 2; ++mi)
#pragma unroll
            for (int p = 0; p < 4; ++p)
#pragma unroll
                for (int c = 0; c < 4; ++c) acc[mi][p][c] = 0.f;

#pragma unroll
        for (int kk = 0; kk < 8; ++kk) {
            uint32_t a0[4], a1[4], b0[4], b1[4];
            LDSM4(a0, aAddr[0] + kk * 32);
            LDSM4(a1, aAddr[1] + kk * 32);
            LDSM4(b0, bAddr[0] + bufoff + kk * 32);
            LDSM4(b1, bAddr[1] + bufoff + kk * 32);
            MMA16816(acc[0][0], a0, b0[0], b0[1]);
            MMA16816(acc[0][1], a0, b0[2], b0[3]);
            MMA16816(acc[0][2], a0, b1[0], b1[1]);
            MMA16816(acc[0][3], a0, b1[2], b1[3]);
            MMA16816(acc[1][0], a1, b0[0], b0[1]);
            MMA16816(acc[1][1], a1, b0[2], b0[3]);
            MMA16816(acc[1][2], a1, b1[0], b1[1]);
            MMA16816(acc[1][3], a1, b1[2], b1[3]);
        }

        // fused epilogue: exp / class-mask stats
        const int* yjs = reinterpret_cast<const int*>(smem + YJ_OFF + (t & 1) * 512);
#pragma unroll
        for (int p = 0; p < 4; ++p) {
            const int jloc = wj * 32 + (p >> 1) * 16 + (p & 1) * 8 + 2 * (lane & 3);
            const int j0 = jbase + jloc, j1 = j0 + 1;
            const int yj0 = yjs[jloc], yj1 = yjs[jloc + 1];
#pragma unroll
            for (int mi = 0; mi < 2; ++mi) {
#pragma unroll
                for (int rh = 0; rh < 2; ++rh) {
                    const int ig = ibase + wi * 32 + mi * 16 + rh * 8 + grp;
                    const float d0 = acc[mi][p][rh * 2 + 0];
                    const float d1 = acc[mi][p][rh * 2 + 1];
                    const float e0 = __expf(10.0f * d0);
                    const float e1 = __expf(10.0f * d1);
                    if (j0 != ig) {
                        dnm[mi][rh] += e0;
                        if (yj0 == yiv[mi][rh]) { Ssum[mi][rh] += d0; msum[mi][rh] += 1.f; }
                    }
                    if (j1 != ig) {
                        dnm[mi][rh] += e1;
                        if (yj1 == yiv[mi][rh]) { Ssum[mi][rh] += d1; msum[mi][rh] += 1.f; }
                    }
                }
            }
        }

        __syncthreads();                        // everyone done with buf(t&1)
        if (t + 2 < 32) {
            uint32_t dstb = sbase + B_OFF + bufoff;
            const int jb = jorig + (t + 2) * 128;
#pragma unroll
            for (int q = 0; q < 4; ++q) {
                int idx = tid + q * THREADS;
                int row = idx >> 4, c16 = idx & 15;
                CP_ASYNC16(dstb + row * STRIDE_B + c16 * 16,
                           (const void*)(xg + (jb + row) * 16 + c16));
            }
            if (tid < 128) CP_ASYNC4(sbase + YJ_OFF + (t & 1) * 512 + tid * 4,
                                     (const void*)(y + jb + tid));
        }
        CP_COMMIT();
    }

    // reduce within warp (lanes sharing same rows: lane&3), then across wj warps
    float* sdd = reinterpret_cast<float*>(smem + SD_OFF);
    float* sds = sdd + 512;
    float* sdm = sdd + 1024;
#pragma unroll
    for (int mi = 0; mi < 2; ++mi)
#pragma unroll
        for (int rh = 0; rh < 2; ++rh) {
            float d = dnm[mi][rh], s = Ssum[mi][rh], m = msum[mi][rh];
            d += __shfl_xor_sync(0xffffffffu, d, 1); d += __shfl_xor_sync(0xffffffffu, d, 2);
            s += __shfl_xor_sync(0xffffffffu, s, 1); s += __shfl_xor_sync(0xffffffffu, s, 2);
            m += __shfl_xor_sync(0xffffffffu, m, 1); m += __shfl_xor_sync(0xffffffffu, m, 2);
            if ((lane & 3) == 0) {
                int rowloc = wi * 32 + mi * 16 + rh * 8 + grp;
                sdd[rowloc * 4 + wj] = d;
                sds[rowloc * 4 + wj] = s;
                sdm[rowloc * 4 + wj] = m;
            }
        }
    __syncthreads();
    if (tid < 128) {
        float d = 0.f, s = 0.f, m = 0.f;
#pragma unroll
        for (int c = 0; c < 4; ++c) {
            d += sdd[tid * 4 + c]; s += sds[tid * 4 + c]; m += sdm[tid * 4 + c];
        }
        int gi = blockIdx.y * NROW + ibase + tid;
        g_pd[gi] = d; g_ps[gi] = s; g_pm[gi] = m;
    }
}

// ---------------- Kernel 3: finish ----------------
__global__ void __launch_bounds__(256) finish_kernel(float* __restrict__ out) {
    __shared__ float red[256];
    float acc = 0.f;
    for (int i = threadIdx.x; i < NROW; i += 256) {
        float d = g_pd[i] + g_pd[NROW + i];
        float s = g_ps[i] + g_ps[NROW + i];
        float m = g_pm[i] + g_pm[NROW + i];
        acc += (m > 0.5f) ? (logf(d) - 10.0f * s / m) : 0.0f;
    }
    red[threadIdx.x] = acc;
    __syncthreads();
#pragma unroll
    for (int o = 128; o; o >>= 1) {
        if (threadIdx.x < o) red[threadIdx.x] += red[threadIdx.x + o];
        __syncthreads();
    }
    if (threadIdx.x == 0) out[0] = red[0];
}

// ---------------------------------------------------------------------------
extern "C" void kernel_launch(void* const* d_in, const int* in_sizes, int n_in,
                              void* d_out, int out_size) {
    (void)in_sizes; (void)n_in; (void)out_size;
    const float* x = (const float*)d_in[0];
    const int*   y = (const int*)d_in[1];
    float* out = (float*)d_out;

    cudaFuncSetAttribute(scl_mma_kernel,
                         cudaFuncAttributeMaxDynamicSharedMemorySize, SMEM_TOTAL);

    norm_kernel<<<NROW / 8, 256>>>(x);
    scl_mma_kernel<<<dim3(64, 2), THREADS, SMEM_TOTAL>>>(y);
    finish_kernel<<<1, 256>>>(out);
}

// round 8
// speedup vs baseline: 7.6399x; 1.4324x over previous
#include <cuda_runtime.h>
#include <cuda_bf16.h>
#include <stdint.h>
#include <math.h>

#define NROW 8192
#define THREADS 512
#define NTILES 2080              // 64*65/2 upper-triangle 128x128 tiles
#define GRID 148
#define STRIDE_B 272u            // 136 bf16 per smem row (17x16B, conflict-free)
#define TILEB (128u * STRIDE_B)  // 34816
#define BUFOFF(b) ((uint32_t)(b) * 2u * TILEB)   // A at +0, B at +TILEB
#define YOFF  (4u * TILEB)                        // 2 bufs x 1024B (yI 512 | yJ 512)
#define IRED  (YOFF + 2048u)                      // 3 x 512 floats
#define JRED  (IRED + 6144u)                      // 3 x 512 floats
#define SMEM_TOTAL (JRED + 6144u)

#define PLANE 524288             // 64*64*128 floats per stat plane

__device__ __nv_bfloat16 g_xb[NROW * 128];
// P[s][a][b][r]: s=0 denom, 1 S, 2 m. Every slot written exactly once per launch.
__device__ float g_P[3 * PLANE];
__device__ float g_row[NROW];

// ---------------- PTX helpers ----------------
__device__ __forceinline__ uint32_t smem_u32(const void* p) {
    uint32_t a;
    asm("{ .reg .u64 t; cvta.to.shared.u64 t, %1; cvt.u32.u64 %0, t; }" : "=r"(a) : "l"(p));
    return a;
}
#define LDSM4(r, a) \
    asm volatile("ldmatrix.sync.aligned.m8n8.x4.shared.b16 {%0,%1,%2,%3}, [%4];" \
        : "=r"((r)[0]), "=r"((r)[1]), "=r"((r)[2]), "=r"((r)[3]) : "r"(a))
#define MMA16816(c, a, b0v, b1v) \
    asm volatile("mma.sync.aligned.m16n8k16.row.col.f32.bf16.bf16.f32 " \
        "{%0,%1,%2,%3}, {%4,%5,%6,%7}, {%8,%9}, {%0,%1,%2,%3};" \
        : "+f"((c)[0]), "+f"((c)[1]), "+f"((c)[2]), "+f"((c)[3]) \
        : "r"((a)[0]), "r"((a)[1]), "r"((a)[2]), "r"((a)[3]), "r"(b0v), "r"(b1v))
#define CP_ASYNC16(dst, src) \
    asm volatile("cp.async.cg.shared.global [%0], [%1], 16;" :: "r"(dst), "l"(src))
#define CP_ASYNC4(dst, src) \
    asm volatile("cp.async.ca.shared.global [%0], [%1], 4;" :: "r"(dst), "l"(src))
#define CP_COMMIT() asm volatile("cp.async.commit_group;" ::: "memory")
#define CP_WAIT1()  asm volatile("cp.async.wait_group 1;" ::: "memory")
#define CP_WAIT0()  asm volatile("cp.async.wait_group 0;" ::: "memory")

// ---------------- Kernel 1: normalize + bf16 convert ----------------
__global__ void __launch_bounds__(256) norm_kernel(const float* __restrict__ x) {
    int row = blockIdx.x * 8 + (threadIdx.x >> 5);
    int lane = threadIdx.x & 31;
    float4 v = reinterpret_cast<const float4*>(x)[row * 32 + lane];
    float ss = v.x * v.x + v.y * v.y + v.z * v.z + v.w * v.w;
#pragma unroll
    for (int o = 16; o; o >>= 1) ss += __shfl_xor_sync(0xffffffffu, ss, o);
    float inv = 1.0f / fmaxf(sqrtf(ss), 1e-12f);
    v.x *= inv; v.y *= inv; v.z *= inv; v.w *= inv;
    uint32_t p0 = ((uint32_t)__bfloat16_as_ushort(__float2bfloat16(v.y)) << 16)
                |  (uint32_t)__bfloat16_as_ushort(__float2bfloat16(v.x));
    uint32_t p1 = ((uint32_t)__bfloat16_as_ushort(__float2bfloat16(v.w)) << 16)
                |  (uint32_t)__bfloat16_as_ushort(__float2bfloat16(v.z));
    reinterpret_cast<uint2*>(g_xb)[row * 32 + lane] = make_uint2(p0, p1);
}

// ---------------- tile id -> (bi, bj), bi <= bj ----------------
__device__ __forceinline__ void tile2bibj(int t, int& bi, int& bj) {
    int rem = (NTILES - 1) - t;
    int k = (int)((__fsqrt_rn(8.0f * (float)rem + 1.0f) - 1.0f) * 0.5f);
    while ((k + 1) * (k + 2) / 2 <= rem) ++k;
    while (k * (k + 1) / 2 > rem) --k;
    int off = rem - k * (k + 1) / 2;
    bi = 63 - k;
    bj = 63 - off;
}

__device__ __forceinline__ void prefetch_tile(uint32_t sbase, int buf,
                                              int bi, int bj, const uint4* xg,
                                              const int* y, int tid) {
    uint32_t dst = sbase + BUFOFF(buf);
    const int arow = bi * 128, brow = bj * 128;
#pragma unroll
    for (int q = 0; q < 4; ++q) {
        int idx = tid + q * THREADS;
        int row = idx >> 4, c16 = idx & 15;
        CP_ASYNC16(dst + row * STRIDE_B + c16 * 16, (const void*)(xg + (arow + row) * 16 + c16));
    }
#pragma unroll
    for (int q = 0; q < 4; ++q) {
        int idx = tid + q * THREADS;
        int row = idx >> 4, c16 = idx & 15;
        CP_ASYNC16(dst + TILEB + row * STRIDE_B + c16 * 16, (const void*)(xg + (brow + row) * 16 + c16));
    }
    if (tid < 128)
        CP_ASYNC4(sbase + YOFF + (uint32_t)buf * 1024u + tid * 4, (const void*)(y + arow + tid));
    else if (tid < 256)
        CP_ASYNC4(sbase + YOFF + (uint32_t)buf * 1024u + 512u + (tid - 128) * 4,
                  (const void*)(y + brow + (tid - 128)));
    CP_COMMIT();
}

// ---------------- Kernel 2: symmetric Gram + dual-orientation stats ----------------
__global__ void __launch_bounds__(THREADS, 1) scl_mma_kernel(const int* __restrict__ y) {
    extern __shared__ char smem[];
    const uint32_t sbase = smem_u32(smem);
    const int tid = threadIdx.x, wid = tid >> 5, lane = tid & 31;
    const int wi = wid & 3, wj = wid >> 2;
    const int grp = lane >> 2;

    const uint4* xg = reinterpret_cast<const uint4*>(g_xb);
    float* iE = reinterpret_cast<float*>(smem + IRED);
    float* iS = iE + 512; float* iM = iE + 1024;
    float* jE = reinterpret_cast<float*>(smem + JRED);
    float* jS = jE + 512; float* jM = jE + 1024;

    // relative ldmatrix offsets (buffer base added per tile)
    uint32_t aRel[2], bRel[2];
#pragma unroll
    for (int mi = 0; mi < 2; ++mi)
        aRel[mi] = (uint32_t)((wi * 32 + mi * 16 + (lane & 15)) * STRIDE_B + (lane >> 4) * 16);
#pragma unroll
    for (int nb = 0; nb < 2; ++nb)
        bRel[nb] = (uint32_t)((wj * 32 + nb * 16 + (lane & 7) + (lane >> 4) * 8) * STRIDE_B
                   + ((lane >> 3) & 1) * 16);

    int t = blockIdx.x;
    {
        int bi, bj; tile2bibj(t, bi, bj);
        prefetch_tile(sbase, 0, bi, bj, xg, y, tid);
    }

    int it = 0;
    for (; t < NTILES; t += GRID, ++it) {
        int bi, bj; tile2bibj(t, bi, bj);
        const int nt = t + GRID;
        if (nt < NTILES) {
            int nbi, nbj; tile2bibj(nt, nbi, nbj);
            prefetch_tile(sbase, (it + 1) & 1, nbi, nbj, xg, y, tid);
            CP_WAIT1();
        } else {
            CP_WAIT0();
        }
        __syncthreads();

        const uint32_t abase = sbase + BUFOFF(it & 1);
        const uint32_t bbase = abase + TILEB;
        const int* yI = reinterpret_cast<const int*>(smem + YOFF + (it & 1) * 1024);
        const int* yJ = yI + 128;
        const bool isDiag = (bi == bj);

        float acc[2][4][4];
#pragma unroll
        for (int mi = 0; mi < 2; ++mi)
#pragma unroll
            for (int p = 0; p < 4; ++p)
#pragma unroll
                for (int c = 0; c < 4; ++c) acc[mi][p][c] = 0.f;

#pragma unroll
        for (int kk = 0; kk < 8; ++kk) {
            uint32_t a0[4], a1[4], b0[4], b1[4];
            LDSM4(a0, abase + aRel[0] + kk * 32);
            LDSM4(a1, abase + aRel[1] + kk * 32);
            LDSM4(b0, bbase + bRel[0] + kk * 32);
            LDSM4(b1, bbase + bRel[1] + kk * 32);
            MMA16816(acc[0][0], a0, b0[0], b0[1]);
            MMA16816(acc[0][1], a0, b0[2], b0[3]);
            MMA16816(acc[0][2], a0, b1[0], b1[1]);
            MMA16816(acc[0][3], a0, b1[2], b1[3]);
            MMA16816(acc[1][0], a1, b0[0], b0[1]);
            MMA16816(acc[1][1], a1, b0[2], b0[3]);
            MMA16816(acc[1][2], a1, b1[0], b1[1]);
            MMA16816(acc[1][3], a1, b1[2], b1[3]);
        }

        int yiv[2][2];
#pragma unroll
        for (int mi = 0; mi < 2; ++mi)
#pragma unroll
            for (int rh = 0; rh < 2; ++rh)
                yiv[mi][rh] = yI[wi * 32 + mi * 16 + rh * 8 + grp];

        float dnm[2][2] = {{0.f,0.f},{0.f,0.f}};
        float Ss [2][2] = {{0.f,0.f},{0.f,0.f}};
        float mm [2][2] = {{0.f,0.f},{0.f,0.f}};

        if (!isDiag) {
#pragma unroll
            for (int p = 0; p < 4; ++p) {
                const int jl = wj * 32 + (p >> 1) * 16 + (p & 1) * 8 + 2 * (lane & 3);
                const int yj0 = yJ[jl], yj1 = yJ[jl + 1];
                float cE0=0.f,cE1=0.f,cS0=0.f,cS1=0.f,cM0=0.f,cM1=0.f;
#pragma unroll
                for (int mi = 0; mi < 2; ++mi)
#pragma unroll
                    for (int rh = 0; rh < 2; ++rh) {
                        const float d0 = acc[mi][p][rh * 2 + 0];
                        const float d1 = acc[mi][p][rh * 2 + 1];
                        const float e0 = __expf(10.0f * d0);
                        const float e1 = __expf(10.0f * d1);
                        const int yi = yiv[mi][rh];
                        dnm[mi][rh] += e0 + e1;
                        cE0 += e0; cE1 += e1;
                        if (yj0 == yi) { Ss[mi][rh] += d0; mm[mi][rh] += 1.f; cS0 += d0; cM0 += 1.f; }
                        if (yj1 == yi) { Ss[mi][rh] += d1; mm[mi][rh] += 1.f; cS1 += d1; cM1 += 1.f; }
                    }
#pragma unroll
                for (int o = 4; o <= 16; o <<= 1) {
                    cE0 += __shfl_xor_sync(0xffffffffu, cE0, o);
                    cE1 += __shfl_xor_sync(0xffffffffu, cE1, o);
                    cS0 += __shfl_xor_sync(0xffffffffu, cS0, o);
                    cS1 += __shfl_xor_sync(0xffffffffu, cS1, o);
                    cM0 += __shfl_xor_sync(0xffffffffu, cM0, o);
                    cM1 += __shfl_xor_sync(0xffffffffu, cM1, o);
                }
                if (grp == 0) {
                    jE[jl * 4 + wi] = cE0;  jE[(jl + 1) * 4 + wi] = cE1;
                    jS[jl * 4 + wi] = cS0;  jS[(jl + 1) * 4 + wi] = cS1;
                    jM[jl * 4 + wi] = cM0;  jM[(jl + 1) * 4 + wi] = cM1;
                }
            }
        } else {
#pragma unroll
            for (int p = 0; p < 4; ++p) {
                const int jl = wj * 32 + (p >> 1) * 16 + (p & 1) * 8 + 2 * (lane & 3);
                const int yj0 = yJ[jl], yj1 = yJ[jl + 1];
#pragma unroll
                for (int mi = 0; mi < 2; ++mi)
#pragma unroll
                    for (int rh = 0; rh < 2; ++rh) {
                        const float d0 = acc[mi][p][rh * 2 + 0];
                        const float d1 = acc[mi][p][rh * 2 + 1];
                        const float e0 = __expf(10.0f * d0);
                        const float e1 = __expf(10.0f * d1);
                        const int yi = yiv[mi][rh];
                        const int rowloc = wi * 32 + mi * 16 + rh * 8 + grp;
                        dnm[mi][rh] += e0 + e1;
                        if (yj0 == yi) { Ss[mi][rh] += d0; mm[mi][rh] += 1.f; }
                        if (yj1 == yi) { Ss[mi][rh] += d1; mm[mi][rh] += 1.f; }
                        if (jl == rowloc)     { dnm[mi][rh] -= e0; Ss[mi][rh] -= d0; mm[mi][rh] -= 1.f; }
                        if (jl + 1 == rowloc) { dnm[mi][rh] -= e1; Ss[mi][rh] -= d1; mm[mi][rh] -= 1.f; }
                    }
            }
        }

        // i-orientation: reduce across the 4 lanes sharing each row
#pragma unroll
        for (int mi = 0; mi < 2; ++mi)
#pragma unroll
            for (int rh = 0; rh < 2; ++rh) {
                float D = dnm[mi][rh], S = Ss[mi][rh], M = mm[mi][rh];
                D += __shfl_xor_sync(0xffffffffu, D, 1); D += __shfl_xor_sync(0xffffffffu, D, 2);
                S += __shfl_xor_sync(0xffffffffu, S, 1); S += __shfl_xor_sync(0xffffffffu, S, 2);
                M += __shfl_xor_sync(0xffffffffu, M, 1); M += __shfl_xor_sync(0xffffffffu, M, 2);
                if ((lane & 3) == 0) {
                    int row = wi * 32 + mi * 16 + rh * 8 + grp;
                    iE[row * 4 + wj] = D; iS[row * 4 + wj] = S; iM[row * 4 + wj] = M;
                }
            }
        __syncthreads();

        // store phase: every P slot written exactly once across the launch
        if (tid < 128) {
            float D = 0.f, S = 0.f, M = 0.f;
#pragma unroll
            for (int c = 0; c < 4; ++c) {
                D += iE[tid * 4 + c]; S += iS[tid * 4 + c]; M += iM[tid * 4 + c];
            }
            const int base = bi * 8192 + bj * 128 + tid;
            g_P[base] = D; g_P[PLANE + base] = S; g_P[2 * PLANE + base] = M;
        } else if (!isDiag && tid < 256) {
            const int r = tid - 128;
            float D = 0.f, S = 0.f, M = 0.f;
#pragma unroll
            for (int c = 0; c < 4; ++c) {
                D += jE[r * 4 + c]; S += jS[r * 4 + c]; M += jM[r * 4 + c];
            }
            const int base = bj * 8192 + bi * 128 + r;
            g_P[base] = D; g_P[PLANE + base] = S; g_P[2 * PLANE + base] = M;
        }
        // loop-top CP_WAIT + __syncthreads orders red-zone reuse next iteration
    }
}

// ---------------- Kernel 3a: per-row loss ----------------
__global__ void __launch_bounds__(128) finish1_kernel() {
    const int A = blockIdx.x, r = threadIdx.x;
    float D = 0.f, S = 0.f, M = 0.f;
    const int base = A * 8192 + r;
#pragma unroll 8
    for (int c = 0; c < 64; ++c) {
        D += g_P[base + c * 128];
        S += g_P[PLANE + base + c * 128];
        M += g_P[2 * PLANE + base + c * 128];
    }
    g_row[A * 128 + r] = (M > 0.5f) ? (logf(D) - 10.0f * S / M) : 0.0f;
}

// ---------------- Kernel 3b: scalar ----------------
__global__ void __launch_bounds__(256) finish2_kernel(float* __restrict__ out) {
    __shared__ float red[256];
    float acc = 0.f;
    for (int i = threadIdx.x; i < NROW; i += 256) acc += g_row[i];
    red[threadIdx.x] = acc;
    __syncthreads();
#pragma unroll
    for (int o = 128; o; o >>= 1) {
        if (threadIdx.x < o) red[threadIdx.x] += red[threadIdx.x + o];
        __syncthreads();
    }
    if (threadIdx.x == 0) out[0] = red[0];
}

// ---------------------------------------------------------------------------
extern "C" void kernel_launch(void* const* d_in, const int* in_sizes, int n_in,
                              void* d_out, int out_size) {
    (void)in_sizes; (void)n_in; (void)out_size;
    const float* x = (const float*)d_in[0];
    const int*   y = (const int*)d_in[1];
    float* out = (float*)d_out;

    cudaFuncSetAttribute(scl_mma_kernel,
                         cudaFuncAttributeMaxDynamicSharedMemorySize, SMEM_TOTAL);

    norm_kernel<<<NROW / 8, 256>>>(x);
    scl_mma_kernel<<<GRID, THREADS, SMEM_TOTAL>>>(y);
    finish1_kernel<<<64, 128>>>();
    finish2_kernel<<<1, 256>>>(out);
}

// round 9
// speedup vs baseline: 8.3023x; 1.0867x over previous
#include <cuda_runtime.h>
#include <cuda_bf16.h>
#include <stdint.h>
#include <math.h>

#define NROW 8192
#define THREADS 512
#define NTILES 2080              // 64*65/2 upper-triangle 128x128 tiles
#define GRID 148
#define STRIDE_B 272u            // 136 bf16 per smem row (17x16B, conflict-free)
#define TILEB (128u * STRIDE_B)  // 34816
#define BUFOFF(b) ((uint32_t)(b) * 2u * TILEB)   // A at +0, B at +TILEB
#define YOFF   (4u * TILEB)                       // 139264: 2 bufs x 1024B
#define IP_OFF (YOFF + 2048u)                     // 141312: 3 x 10240B (128 rows x 20 words)
#define JP_OFF (IP_OFF + 30720u)                  // 172032: 3 x 18432B (128 cols x 36 words)
#define SMEM_TOTAL (JP_OFF + 55296u)              // 227328 <= 232448

#define PLANE 524288             // 64*64*128 floats per stat plane

__device__ __nv_bfloat16 g_xb[NROW * 128];
// P[s][a][b][r]: s=0 denom, 1 S, 2 m. Every slot written exactly once per launch.
__device__ float g_P[3 * PLANE];
__device__ float g_part[64];
__device__ int   g_ctr;          // zero-init; self-resets each launch

// ---------------- PTX helpers ----------------
__device__ __forceinline__ uint32_t smem_u32(const void* p) {
    uint32_t a;
    asm("{ .reg .u64 t; cvta.to.shared.u64 t, %1; cvt.u32.u64 %0, t; }" : "=r"(a) : "l"(p));
    return a;
}
#define LDSM4(r, a) \
    asm volatile("ldmatrix.sync.aligned.m8n8.x4.shared.b16 {%0,%1,%2,%3}, [%4];" \
        : "=r"((r)[0]), "=r"((r)[1]), "=r"((r)[2]), "=r"((r)[3]) : "r"(a))
#define MMA16816(c, a, b0v, b1v) \
    asm volatile("mma.sync.aligned.m16n8k16.row.col.f32.bf16.bf16.f32 " \
        "{%0,%1,%2,%3}, {%4,%5,%6,%7}, {%8,%9}, {%0,%1,%2,%3};" \
        : "+f"((c)[0]), "+f"((c)[1]), "+f"((c)[2]), "+f"((c)[3]) \
        : "r"((a)[0]), "r"((a)[1]), "r"((a)[2]), "r"((a)[3]), "r"(b0v), "r"(b1v))
#define CP_ASYNC16(dst, src) \
    asm volatile("cp.async.cg.shared.global [%0], [%1], 16;" :: "r"(dst), "l"(src))
#define CP_ASYNC4(dst, src) \
    asm volatile("cp.async.ca.shared.global [%0], [%1], 4;" :: "r"(dst), "l"(src))
#define CP_COMMIT() asm volatile("cp.async.commit_group;" ::: "memory")
#define CP_WAIT1()  asm volatile("cp.async.wait_group 1;" ::: "memory")
#define CP_WAIT0()  asm volatile("cp.async.wait_group 0;" ::: "memory")

// ---------------- Kernel 1: normalize + bf16 convert (2 rows/warp) ----------------
__global__ void __launch_bounds__(256) norm_kernel(const float* __restrict__ x) {
    int warp = threadIdx.x >> 5, lane = threadIdx.x & 31;
    int row0 = (blockIdx.x * 8 + warp) * 2;
    float4 v0 = reinterpret_cast<const float4*>(x)[row0 * 32 + lane];
    float4 v1 = reinterpret_cast<const float4*>(x)[(row0 + 1) * 32 + lane];
    float s0 = v0.x * v0.x + v0.y * v0.y + v0.z * v0.z + v0.w * v0.w;
    float s1 = v1.x * v1.x + v1.y * v1.y + v1.z * v1.z + v1.w * v1.w;
#pragma unroll
    for (int o = 16; o; o >>= 1) {
        s0 += __shfl_xor_sync(0xffffffffu, s0, o);
        s1 += __shfl_xor_sync(0xffffffffu, s1, o);
    }
    float i0 = 1.0f / fmaxf(sqrtf(s0), 1e-12f);
    float i1 = 1.0f / fmaxf(sqrtf(s1), 1e-12f);
    v0.x *= i0; v0.y *= i0; v0.z *= i0; v0.w *= i0;
    v1.x *= i1; v1.y *= i1; v1.z *= i1; v1.w *= i1;
    uint32_t a0 = ((uint32_t)__bfloat16_as_ushort(__float2bfloat16(v0.y)) << 16)
                |  (uint32_t)__bfloat16_as_ushort(__float2bfloat16(v0.x));
    uint32_t a1 = ((uint32_t)__bfloat16_as_ushort(__float2bfloat16(v0.w)) << 16)
                |  (uint32_t)__bfloat16_as_ushort(__float2bfloat16(v0.z));
    uint32_t b0 = ((uint32_t)__bfloat16_as_ushort(__float2bfloat16(v1.y)) << 16)
                |  (uint32_t)__bfloat16_as_ushort(__float2bfloat16(v1.x));
    uint32_t b1 = ((uint32_t)__bfloat16_as_ushort(__float2bfloat16(v1.w)) << 16)
                |  (uint32_t)__bfloat16_as_ushort(__float2bfloat16(v1.z));
    reinterpret_cast<uint2*>(g_xb)[row0 * 32 + lane] = make_uint2(a0, a1);
    reinterpret_cast<uint2*>(g_xb)[(row0 + 1) * 32 + lane] = make_uint2(b0, b1);
}

// ---------------- tile id -> (bi, bj), bi <= bj ----------------
__device__ __forceinline__ void tile2bibj(int t, int& bi, int& bj) {
    int rem = (NTILES - 1) - t;
    int k = (int)((__fsqrt_rn(8.0f * (float)rem + 1.0f) - 1.0f) * 0.5f);
    while ((k + 1) * (k + 2) / 2 <= rem) ++k;
    while (k * (k + 1) / 2 > rem) --k;
    int off = rem - k * (k + 1) / 2;
    bi = 63 - k;
    bj = 63 - off;
}

__device__ __forceinline__ void prefetch_tile(uint32_t sbase, int buf,
                                              int bi, int bj, const uint4* xg,
                                              const int* y, int tid) {
    uint32_t dst = sbase + BUFOFF(buf);
    const int arow = bi * 128, brow = bj * 128;
#pragma unroll
    for (int q = 0; q < 4; ++q) {
        int idx = tid + q * THREADS;
        int row = idx >> 4, c16 = idx & 15;
        CP_ASYNC16(dst + row * STRIDE_B + c16 * 16, (const void*)(xg + (arow + row) * 16 + c16));
    }
#pragma unroll
    for (int q = 0; q < 4; ++q) {
        int idx = tid + q * THREADS;
        int row = idx >> 4, c16 = idx & 15;
        CP_ASYNC16(dst + TILEB + row * STRIDE_B + c16 * 16, (const void*)(xg + (brow + row) * 16 + c16));
    }
    if (tid < 128)
        CP_ASYNC4(sbase + YOFF + (uint32_t)buf * 1024u + tid * 4, (const void*)(y + arow + tid));
    else if (tid < 256)
        CP_ASYNC4(sbase + YOFF + (uint32_t)buf * 1024u + 512u + (tid - 128) * 4,
                  (const void*)(y + brow + (tid - 128)));
    CP_COMMIT();
}

// ---------------- Kernel 2: symmetric Gram + dual-orientation stats ----------------
__global__ void __launch_bounds__(THREADS, 1) scl_mma_kernel(const int* __restrict__ y) {
    extern __shared__ char smem[];
    const uint32_t sbase = smem_u32(smem);
    const int tid = threadIdx.x, wid = tid >> 5, lane = tid & 31;
    const int wi = wid & 3, wj = wid >> 2;
    const int grp = lane >> 2;

    const uint4* xg = reinterpret_cast<const uint4*>(g_xb);
    float* ipE = reinterpret_cast<float*>(smem + IP_OFF);          // 128 x 20 words
    float* ipS = ipE + 2560; float* ipM = ipE + 5120;
    float* jpE = reinterpret_cast<float*>(smem + JP_OFF);          // 128 x 36 words
    float* jpS = jpE + 4608; float* jpM = jpE + 9216;

    // relative ldmatrix offsets (buffer base added per tile)
    uint32_t aRel[2], bRel[2];
#pragma unroll
    for (int mi = 0; mi < 2; ++mi)
        aRel[mi] = (uint32_t)((wi * 32 + mi * 16 + (lane & 15)) * STRIDE_B + (lane >> 4) * 16);
#pragma unroll
    for (int nb = 0; nb < 2; ++nb)
        bRel[nb] = (uint32_t)((wj * 32 + nb * 16 + (lane & 7) + (lane >> 4) * 8) * STRIDE_B
                   + ((lane >> 3) & 1) * 16);

    int t = blockIdx.x;
    {
        int bi, bj; tile2bibj(t, bi, bj);
        prefetch_tile(sbase, 0, bi, bj, xg, y, tid);
    }

    int it = 0;
    for (; t < NTILES; t += GRID, ++it) {
        int bi, bj; tile2bibj(t, bi, bj);
        const int nt = t + GRID;
        if (nt < NTILES) {
            int nbi, nbj; tile2bibj(nt, nbi, nbj);
            prefetch_tile(sbase, (it + 1) & 1, nbi, nbj, xg, y, tid);
            CP_WAIT1();
        } else {
            CP_WAIT0();
        }
        __syncthreads();

        const uint32_t abase = sbase + BUFOFF(it & 1);
        const uint32_t bbase = abase + TILEB;
        const int* yI = reinterpret_cast<const int*>(smem + YOFF + (it & 1) * 1024);
        const int* yJ = yI + 128;
        const bool isDiag = (bi == bj);

        float acc[2][4][4];
#pragma unroll
        for (int mi = 0; mi < 2; ++mi)
#pragma unroll
            for (int p = 0; p < 4; ++p)
#pragma unroll
                for (int c = 0; c < 4; ++c) acc[mi][p][c] = 0.f;

#pragma unroll
        for (int kk = 0; kk < 8; ++kk) {
            uint32_t a0[4], a1[4], b0[4], b1[4];
            LDSM4(a0, abase + aRel[0] + kk * 32);
            LDSM4(a1, abase + aRel[1] + kk * 32);
            LDSM4(b0, bbase + bRel[0] + kk * 32);
            LDSM4(b1, bbase + bRel[1] + kk * 32);
            MMA16816(acc[0][0], a0, b0[0], b0[1]);
            MMA16816(acc[0][1], a0, b0[2], b0[3]);
            MMA16816(acc[0][2], a0, b1[0], b1[1]);
            MMA16816(acc[0][3], a0, b1[2], b1[3]);
            MMA16816(acc[1][0], a1, b0[0], b0[1]);
            MMA16816(acc[1][1], a1, b0[2], b0[3]);
            MMA16816(acc[1][2], a1, b1[0], b1[1]);
            MMA16816(acc[1][3], a1, b1[2], b1[3]);
        }

        int yiv[2][2];
#pragma unroll
        for (int mi = 0; mi < 2; ++mi)
#pragma unroll
            for (int rh = 0; rh < 2; ++rh)
                yiv[mi][rh] = yI[wi * 32 + mi * 16 + rh * 8 + grp];

        float dnm[2][2] = {{0.f,0.f},{0.f,0.f}};
        float Ss [2][2] = {{0.f,0.f},{0.f,0.f}};
        float mm [2][2] = {{0.f,0.f},{0.f,0.f}};

        if (!isDiag) {
#pragma unroll
            for (int p = 0; p < 4; ++p) {
                const int jl = wj * 32 + (p >> 1) * 16 + (p & 1) * 8 + 2 * (lane & 3);
                const int yj0 = yJ[jl], yj1 = yJ[jl + 1];
                float cE0=0.f,cE1=0.f,cS0=0.f,cS1=0.f,cM0=0.f,cM1=0.f;
#pragma unroll
                for (int mi = 0; mi < 2; ++mi)
#pragma unroll
                    for (int rh = 0; rh < 2; ++rh) {
                        const float d0 = acc[mi][p][rh * 2 + 0];
                        const float d1 = acc[mi][p][rh * 2 + 1];
                        const float e0 = __expf(10.0f * d0);
                        const float e1 = __expf(10.0f * d1);
                        const int yi = yiv[mi][rh];
                        const float m0 = (yj0 == yi) ? 1.0f : 0.0f;
                        const float m1 = (yj1 == yi) ? 1.0f : 0.0f;
                        dnm[mi][rh] += e0 + e1;
                        Ss[mi][rh]  = fmaf(d0, m0, fmaf(d1, m1, Ss[mi][rh]));
                        mm[mi][rh] += m0 + m1;
                        cE0 += e0; cE1 += e1;
                        cS0 = fmaf(d0, m0, cS0); cS1 = fmaf(d1, m1, cS1);
                        cM0 += m0; cM1 += m1;
                    }
                const int s0 = jl * 36 + wi * 8 + grp, s1 = s0 + 36;
                jpE[s0] = cE0; jpE[s1] = cE1;
                jpS[s0] = cS0; jpS[s1] = cS1;
                jpM[s0] = cM0; jpM[s1] = cM1;
            }
        } else {
#pragma unroll
            for (int p = 0; p < 4; ++p) {
                const int jl = wj * 32 + (p >> 1) * 16 + (p & 1) * 8 + 2 * (lane & 3);
                const int yj0 = yJ[jl], yj1 = yJ[jl + 1];
#pragma unroll
                for (int mi = 0; mi < 2; ++mi)
#pragma unroll
                    for (int rh = 0; rh < 2; ++rh) {
                        const float d0 = acc[mi][p][rh * 2 + 0];
                        const float d1 = acc[mi][p][rh * 2 + 1];
                        float e0 = __expf(10.0f * d0);
                        float e1 = __expf(10.0f * d1);
                        const int yi = yiv[mi][rh];
                        const int rowloc = wi * 32 + mi * 16 + rh * 8 + grp;
                        float m0 = (yj0 == yi) ? 1.0f : 0.0f;
                        float m1 = (yj1 == yi) ? 1.0f : 0.0f;
                        if (jl == rowloc)     { e0 = 0.0f; m0 = 0.0f; }
                        if (jl + 1 == rowloc) { e1 = 0.0f; m1 = 0.0f; }
                        dnm[mi][rh] += e0 + e1;
                        Ss[mi][rh]  = fmaf(d0, m0, fmaf(d1, m1, Ss[mi][rh]));
                        mm[mi][rh] += m0 + m1;
                    }
            }
        }

        // i-orientation per-thread partials: row slot = row*20 + wj*4 + (lane&3)
#pragma unroll
        for (int mi = 0; mi < 2; ++mi)
#pragma unroll
            for (int rh = 0; rh < 2; ++rh) {
                const int row = wi * 32 + mi * 16 + rh * 8 + grp;
                const int sl = row * 20 + wj * 4 + (lane & 3);
                ipE[sl] = dnm[mi][rh]; ipS[sl] = Ss[mi][rh]; ipM[sl] = mm[mi][rh];
            }
        __syncthreads();

        // store phase: sum partials, write g_P (each slot exactly once per launch)
        const int ntask = isDiag ? 384 : 768;
        for (int task = tid; task < ntask; task += THREADS) {
            if (task < 384) {
                const int stat = task >> 7, row = task & 127;
                const float* src = ipE + stat * 2560 + row * 20;
                float s = 0.f;
#pragma unroll
                for (int q = 0; q < 4; ++q) {
                    float4 v = *reinterpret_cast<const float4*>(src + q * 4);
                    s += (v.x + v.y) + (v.z + v.w);
                }
                g_P[stat * PLANE + bi * 8192 + bj * 128 + row] = s;
            } else {
                const int tt = task - 384;
                const int stat = tt >> 7, col = tt & 127;
                const float* src = jpE + stat * 4608 + col * 36;
                float s = 0.f;
#pragma unroll
                for (int q = 0; q < 8; ++q) {
                    float4 v = *reinterpret_cast<const float4*>(src + q * 4);
                    s += (v.x + v.y) + (v.z + v.w);
                }
                g_P[stat * PLANE + bj * 8192 + bi * 128 + col] = s;
            }
        }
        // loop-top CP_WAIT + __syncthreads orders partial-zone reuse next iteration
    }
}

// ---------------- Kernel 3: fused per-row loss + global sum ----------------
__global__ void __launch_bounds__(128) finish_kernel(float* __restrict__ out) {
    const int A = blockIdx.x, r = threadIdx.x;
    float D = 0.f, S = 0.f, M = 0.f;
    const int base = A * 8192 + r;
#pragma unroll 8
    for (int c = 0; c < 64; ++c) {
        D += g_P[base + c * 128];
        S += g_P[PLANE + base + c * 128];
        M += g_P[2 * PLANE + base + c * 128];
    }
    float v = (M > 0.5f) ? (logf(D) - 10.0f * S / M) : 0.0f;
    __shared__ float red[4];
#pragma unroll
    for (int o = 16; o; o >>= 1) v += __shfl_xor_sync(0xffffffffu, v, o);
    if ((r & 31) == 0) red[r >> 5] = v;
    __syncthreads();
    if (r == 0) {
        g_part[A] = (red[0] + red[1]) + (red[2] + red[3]);
        __threadfence();
        if (atomicAdd(&g_ctr, 1) == 63) {
            float s = 0.f;
#pragma unroll 8
            for (int i = 0; i < 64; ++i) s += g_part[i];
            out[0] = s;
            g_ctr = 0;     // reset for graph replay
        }
    }
}

// ---------------------------------------------------------------------------
extern "C" void kernel_launch(void* const* d_in, const int* in_sizes, int n_in,
                              void* d_out, int out_size) {
    (void)in_sizes; (void)n_in; (void)out_size;
    const float* x = (const float*)d_in[0];
    const int*   y = (const int*)d_in[1];
    float* out = (float*)d_out;

    cudaFuncSetAttribute(scl_mma_kernel,
                         cudaFuncAttributeMaxDynamicSharedMemorySize, SMEM_TOTAL);

    norm_kernel<<<NROW / 16, 256>>>(x);
    scl_mma_kernel<<<GRID, THREADS, SMEM_TOTAL>>>(y);
    finish_kernel<<<64, 128>>>(out);
}